// round 4
// baseline (speedup 1.0000x reference)
#include <cuda_runtime.h>
#include <math.h>
#include <stdint.h>

#define BATCH 4
#define SEQ   4096
#define HDIM  64
#define BQ    64                 // queries per block
#define BK    32                 // keys per tile
#define NTILES (SEQ / BK)
#define THREADS 256              // 4 lanes per query * 64 queries
#define F4_PER_TILE (BK * HDIM / 4)   // 512 float4 per K (or V) tile

__device__ __forceinline__ void cp_async16(void* smem, const void* gmem) {
    uint32_t s = (uint32_t)__cvta_generic_to_shared(smem);
    asm volatile("cp.async.cg.shared.global [%0], [%1], 16;\n" :: "r"(s), "l"(gmem));
}
__device__ __forceinline__ void cp_commit() {
    asm volatile("cp.async.commit_group;\n");
}
template<int N>
__device__ __forceinline__ void cp_wait() {
    asm volatile("cp.async.wait_group %0;\n" :: "n"(N));
}

// 4 lanes per query: lane c = lane&3 owns dims [16c, 16c+16).
// Full-row online softmax (stats over ALL keys); V accumulation causal-gated.
__global__ __launch_bounds__(THREADS, 2)
void attn_fullsoftmax_causal_kernel(const float* __restrict__ qg,
                                    const float* __restrict__ kg,
                                    const float* __restrict__ vg,
                                    float* __restrict__ outg) {
    __shared__ float4 Kbuf[2][F4_PER_TILE];
    __shared__ float4 Vbuf[2][F4_PER_TILE];

    const int b    = blockIdx.y;
    const int t    = threadIdx.x;
    const int wid  = t >> 5;
    const int lane = t & 31;
    const int ql   = lane >> 2;          // query-in-warp (0..7)
    const int c    = lane & 3;           // dim chunk (0..3)
    const int qi   = blockIdx.x * BQ + wid * 8 + ql;   // global query index

    // ---- load this lane's 16-dim query chunk, pre-scaled by 1/sqrt(D)=0.125
    const float4* qrow = (const float4*)(qg + ((size_t)b * SEQ + qi) * HDIM) + c * 4;
    float4 qr[4];
    #pragma unroll
    for (int i = 0; i < 4; i++) {
        float4 x = qrow[i];
        x.x *= 0.125f; x.y *= 0.125f; x.z *= 0.125f; x.w *= 0.125f;
        qr[i] = x;
    }

    float acc[16];
    #pragma unroll
    for (int d = 0; d < 16; d++) acc[d] = 0.0f;
    float m = -INFINITY;
    float l = 0.0f;

    const float4* kbase = (const float4*)(kg + (size_t)b * SEQ * HDIM);
    const float4* vbase = (const float4*)(vg + (size_t)b * SEQ * HDIM);

    // ---- prologue: async-load tile 0 into buffer 0
    {
        const float4* ks = kbase;            // tile 0
        const float4* vs = vbase;
        #pragma unroll
        for (int r = 0; r < F4_PER_TILE / THREADS; r++) {
            int idx = t + r * THREADS;
            cp_async16(&Kbuf[0][idx], &ks[idx]);
            cp_async16(&Vbuf[0][idx], &vs[idx]);
        }
        cp_commit();
    }

    for (int kt = 0; kt < NTILES; kt++) {
        const int buf = kt & 1;

        // ---- issue prefetch of next tile into the other buffer
        if (kt + 1 < NTILES) {
            const float4* ks = kbase + (size_t)(kt + 1) * F4_PER_TILE;
            const float4* vs = vbase + (size_t)(kt + 1) * F4_PER_TILE;
            #pragma unroll
            for (int r = 0; r < F4_PER_TILE / THREADS; r++) {
                int idx = t + r * THREADS;
                cp_async16(&Kbuf[buf ^ 1][idx], &ks[idx]);
                cp_async16(&Vbuf[buf ^ 1][idx], &vs[idx]);
            }
            cp_commit();
            cp_wait<1>();    // current tile's group complete; next may be in flight
        } else {
            cp_wait<0>();
        }
        __syncthreads();

        // ---- partial scores on this lane's 16-dim chunk, butterfly to full score
        float sreg[BK];
        float tmax = -INFINITY;
        #pragma unroll
        for (int j = 0; j < BK; j++) {
            const float4* kr = &Kbuf[buf][j * (HDIM / 4) + c * 4];
            float s0 = 0.f, s1 = 0.f, s2 = 0.f, s3 = 0.f;
            #pragma unroll
            for (int i = 0; i < 4; i++) {
                float4 kv = kr[i];
                s0 = fmaf(qr[i].x, kv.x, s0);
                s1 = fmaf(qr[i].y, kv.y, s1);
                s2 = fmaf(qr[i].z, kv.z, s2);
                s3 = fmaf(qr[i].w, kv.w, s3);
            }
            float p = (s0 + s1) + (s2 + s3);
            // reduce across the 4 chunk-lanes of this query (xor 1, xor 2)
            p += __shfl_xor_sync(0xffffffffu, p, 1);
            p += __shfl_xor_sync(0xffffffffu, p, 2);
            sreg[j] = p;
            tmax = fmaxf(tmax, p);
        }

        // ---- online softmax update (stats over ALL keys)
        const float m_new = fmaxf(m, tmax);
        const float corr  = __expf(m - m_new);   // 0 on first tile
        l *= corr;
        #pragma unroll
        for (int d = 0; d < 16; d++) acc[d] *= corr;
        #pragma unroll
        for (int j = 0; j < BK; j++) {
            float p = __expf(sreg[j] - m_new);
            l += p;
            sreg[j] = p;
        }
        m = m_new;

        // ---- causal-gated V accumulation (keys with global index <= qi)
        const int base = kt * BK;
        if (base <= qi) {
            const int jmax = min(BK, qi - base + 1);
            for (int j = 0; j < jmax; j++) {
                const float p = sreg[j];
                const float4* vr = &Vbuf[buf][j * (HDIM / 4) + c * 4];
                #pragma unroll
                for (int i = 0; i < 4; i++) {
                    float4 vv = vr[i];
                    acc[4 * i + 0] = fmaf(p, vv.x, acc[4 * i + 0]);
                    acc[4 * i + 1] = fmaf(p, vv.y, acc[4 * i + 1]);
                    acc[4 * i + 2] = fmaf(p, vv.z, acc[4 * i + 2]);
                    acc[4 * i + 3] = fmaf(p, vv.w, acc[4 * i + 3]);
                }
            }
        }
        __syncthreads();
    }

    // ---- epilogue: divide by full-row partition function, store this chunk
    const float inv_l = 1.0f / l;
    float4* orow = (float4*)(outg + ((size_t)b * SEQ + qi) * HDIM) + c * 4;
    #pragma unroll
    for (int i = 0; i < 4; i++) {
        float4 o;
        o.x = acc[4 * i + 0] * inv_l;
        o.y = acc[4 * i + 1] * inv_l;
        o.z = acc[4 * i + 2] * inv_l;
        o.w = acc[4 * i + 3] * inv_l;
        orow[i] = o;
    }
}

extern "C" void kernel_launch(void* const* d_in, const int* in_sizes, int n_in,
                              void* d_out, int out_size) {
    const float* q = (const float*)d_in[0];
    const float* k = (const float*)d_in[1];
    const float* v = (const float*)d_in[2];
    float* out = (float*)d_out;

    dim3 grid(SEQ / BQ, BATCH);
    dim3 block(THREADS);
    attn_fullsoftmax_causal_kernel<<<grid, block>>>(q, k, v, out);
}

// round 5
// speedup vs baseline: 3.0207x; 3.0207x over previous
#include <cuda_runtime.h>
#include <math.h>
#include <stdint.h>

#define BATCH  4
#define SEQ    4096
#define HDIM   64
#define BQ     64                 // queries per block (= threads per block)
#define BK     16                 // keys per shared tile
#define KSPLIT 8                  // key-range splits (blocks) per query row
#define KEYS_PER_SPLIT (SEQ / KSPLIT)        // 512
#define NTILES_SPLIT   (KEYS_PER_SPLIT / BK) // 32

// Split-K scratch: per (split, b, q): 64 unnormalized acc + m + l.
__device__ float g_acc[KSPLIT * BATCH * SEQ * HDIM];   // 33.5 MB
__device__ float g_m[KSPLIT * BATCH * SEQ];
__device__ float g_l[KSPLIT * BATCH * SEQ];

// One thread per query; each block owns one key-range split.
// Online softmax stats over this split's keys (full-row semantics recovered in merge);
// V accumulation causal-gated (post-softmax causal zeroing).
__global__ __launch_bounds__(BQ, 8)
void attn_splitk_kernel(const float* __restrict__ qg,
                        const float* __restrict__ kg,
                        const float* __restrict__ vg) {
    __shared__ float Ksh[BK][HDIM];
    __shared__ float Vsh[BK][HDIM];

    const int b    = blockIdx.y;
    const int r    = blockIdx.z;                 // key-range split
    const int t    = threadIdx.x;
    const int qi   = blockIdx.x * BQ + t;        // global query index
    const int koff = r * KEYS_PER_SPLIT;         // first key of this split

    // ---- query row into registers, pre-scaled by 1/sqrt(D)=0.125
    const float4* qrow = (const float4*)(qg + ((size_t)b * SEQ + qi) * HDIM);
    float4 qr[HDIM / 4];
    #pragma unroll
    for (int i = 0; i < HDIM / 4; i++) {
        float4 x = qrow[i];
        x.x *= 0.125f; x.y *= 0.125f; x.z *= 0.125f; x.w *= 0.125f;
        qr[i] = x;
    }

    float acc[HDIM];
    #pragma unroll
    for (int d = 0; d < HDIM; d++) acc[d] = 0.0f;
    float m = -INFINITY;
    float l = 0.0f;

    const float* kb = kg + ((size_t)b * SEQ + koff) * HDIM;
    const float* vb = vg + ((size_t)b * SEQ + koff) * HDIM;

    for (int kt = 0; kt < NTILES_SPLIT; kt++) {
        // ---- cooperative tile load: BK*HDIM/4 = 256 float4, 64 threads -> 4 each
        {
            const float4* ks = (const float4*)(kb + (size_t)kt * BK * HDIM);
            const float4* vs = (const float4*)(vb + (size_t)kt * BK * HDIM);
            float4* Kd = (float4*)&Ksh[0][0];
            float4* Vd = (float4*)&Vsh[0][0];
            #pragma unroll
            for (int i = 0; i < (BK * HDIM / 4) / BQ; i++) {
                Kd[t + i * BQ] = ks[t + i * BQ];
                Vd[t + i * BQ] = vs[t + i * BQ];
            }
        }
        __syncthreads();

        // ---- scores (broadcast LDS.128, 4 partial sums for ILP)
        float sreg[BK];
        float tmax = -INFINITY;
        #pragma unroll
        for (int j = 0; j < BK; j++) {
            const float4* kr = (const float4*)Ksh[j];
            float s0 = 0.f, s1 = 0.f, s2 = 0.f, s3 = 0.f;
            #pragma unroll
            for (int i = 0; i < HDIM / 4; i++) {
                float4 kv = kr[i];
                s0 = fmaf(qr[i].x, kv.x, s0);
                s1 = fmaf(qr[i].y, kv.y, s1);
                s2 = fmaf(qr[i].z, kv.z, s2);
                s3 = fmaf(qr[i].w, kv.w, s3);
            }
            float sj = (s0 + s1) + (s2 + s3);
            sreg[j] = sj;
            tmax = fmaxf(tmax, sj);
        }

        // ---- online softmax update (stats over ALL keys in this split)
        const float m_new = fmaxf(m, tmax);
        const float corr  = __expf(m - m_new);   // 0 on first tile (m = -inf)
        l *= corr;
        #pragma unroll
        for (int d = 0; d < HDIM; d++) acc[d] *= corr;
        #pragma unroll
        for (int j = 0; j < BK; j++) {
            float p = __expf(sreg[j] - m_new);
            l += p;
            sreg[j] = p;
        }
        m = m_new;

        // ---- causal-gated V accumulation: keys with global index <= qi
        const int base = koff + kt * BK;
        if (base <= qi) {
            const int jmax = min(BK, qi - base + 1);
            for (int j = 0; j < jmax; j++) {
                const float p = sreg[j];
                const float4* vr = (const float4*)Vsh[j];
                #pragma unroll
                for (int i = 0; i < HDIM / 4; i++) {
                    float4 vv = vr[i];
                    acc[4 * i + 0] = fmaf(p, vv.x, acc[4 * i + 0]);
                    acc[4 * i + 1] = fmaf(p, vv.y, acc[4 * i + 1]);
                    acc[4 * i + 2] = fmaf(p, vv.z, acc[4 * i + 2]);
                    acc[4 * i + 3] = fmaf(p, vv.w, acc[4 * i + 3]);
                }
            }
        }
        __syncthreads();
    }

    // ---- write partials (unnormalized acc + local m, l)
    const size_t bq  = (size_t)b * SEQ + qi;
    const size_t idx = (size_t)r * BATCH * SEQ + bq;
    float4* arow = (float4*)(g_acc + idx * HDIM);
    #pragma unroll
    for (int i = 0; i < HDIM / 4; i++) {
        float4 o;
        o.x = acc[4 * i + 0]; o.y = acc[4 * i + 1];
        o.z = acc[4 * i + 2]; o.w = acc[4 * i + 3];
        arow[i] = o;
    }
    g_m[idx] = m;
    g_l[idx] = l;
}

// Merge KSPLIT partials per query: exact log-sum-exp weighted combine.
// One thread per (b, q, 4-dim chunk): B*S*16 = 262144 threads.
__global__ __launch_bounds__(256)
void attn_merge_kernel(float* __restrict__ outg) {
    const int idx = blockIdx.x * blockDim.x + threadIdx.x;
    const int i4  = idx & 15;               // float4 chunk within head dim
    const int bq  = idx >> 4;               // b*SEQ + q

    float mr[KSPLIT];
    float mstar = -INFINITY;
    #pragma unroll
    for (int r = 0; r < KSPLIT; r++) {
        mr[r] = g_m[(size_t)r * BATCH * SEQ + bq];
        mstar = fmaxf(mstar, mr[r]);
    }

    float lsum = 0.0f;
    float4 o = make_float4(0.f, 0.f, 0.f, 0.f);
    #pragma unroll
    for (int r = 0; r < KSPLIT; r++) {
        const size_t sidx = (size_t)r * BATCH * SEQ + bq;
        const float w = __expf(mr[r] - mstar);
        lsum = fmaf(w, g_l[sidx], lsum);
        const float4 a = ((const float4*)(g_acc + sidx * HDIM))[i4];
        o.x = fmaf(w, a.x, o.x);
        o.y = fmaf(w, a.y, o.y);
        o.z = fmaf(w, a.z, o.z);
        o.w = fmaf(w, a.w, o.w);
    }

    const float inv = 1.0f / lsum;
    o.x *= inv; o.y *= inv; o.z *= inv; o.w *= inv;
    ((float4*)outg)[idx] = o;
}

extern "C" void kernel_launch(void* const* d_in, const int* in_sizes, int n_in,
                              void* d_out, int out_size) {
    const float* q = (const float*)d_in[0];
    const float* k = (const float*)d_in[1];
    const float* v = (const float*)d_in[2];
    float* out = (float*)d_out;

    dim3 grid1(SEQ / BQ, BATCH, KSPLIT);
    attn_splitk_kernel<<<grid1, BQ>>>(q, k, v);

    const int merge_threads = BATCH * SEQ * (HDIM / 4);   // 262144
    attn_merge_kernel<<<merge_threads / 256, 256>>>(out);
}